// round 1
// baseline (speedup 1.0000x reference)
#include <cuda_runtime.h>
#include <cuda_bf16.h>

// ConvSpatialPropagationNet_71949292143069
//
// The reference's propagation body multiplies the (padded) gate tensor by the
// (padded) depth ELEMENTWISE at the same padded coordinate — there is no
// neighbor gather. The per-step update is d <- (1-G)*raw + G*d with d0 = raw,
// whose exact fixed point is d = raw = blur_depth. The mask blend also returns
// raw. All 24 iterations are identity up to ~1e-6 fp32 rounding.
//
// Therefore: out = blur_depth (d_in[1]), a straight 13.7 MB device copy.
// This is the traffic roofline for the problem (read input once, write output
// once). Vectorized float4 copy; N = 8*352*1216 = 3,424,256 is divisible by 4.

__global__ void cspn_identity_copy_kernel(const float4* __restrict__ in,
                                          float4* __restrict__ out,
                                          int n4) {
    int i = blockIdx.x * blockDim.x + threadIdx.x;
    if (i < n4) {
        out[i] = in[i];
    }
}

extern "C" void kernel_launch(void* const* d_in, const int* in_sizes, int n_in,
                              void* d_out, int out_size) {
    // Inputs (metadata order): guidance, blur_depth, sparse_depth, sum_w
    const float* blur_depth = (const float*)d_in[1];
    float* out = (float*)d_out;

    int n = in_sizes[1];           // == out_size == 3,424,256
    int n4 = n >> 2;               // 856,064 float4
    int threads = 256;
    int blocks = (n4 + threads - 1) / threads;

    cspn_identity_copy_kernel<<<blocks, threads>>>(
        (const float4*)blur_depth, (float4*)out, n4);
}